// round 5
// baseline (speedup 1.0000x reference)
#include <cuda_runtime.h>
#include <cuda_fp16.h>
#include <cstdint>
#include <cstddef>

// ----------------------------------------------------------------------------
// out[16384,4096] = spike[16384,4096] @ W[4096,4096] + bias   (fp32 I/O)
// Issue-bound on legacy HMMA -> halve MMA count with 2:4 sparse
// mma.sp::ordered_metadata.m16n8k32. Spikes beyond 2-per-4-group (~0.38% of
// groups) go to a residual list applied exactly in the epilogue.
// ----------------------------------------------------------------------------

static constexpr int MM = 16384, KK = 4096, NN = 4096;
static constexpr int BM = 128, BN = 256, BK = 64;
static constexpr int STAGES = 5;
static constexpr int KTILES = KK / BK;            // 64
static constexpr int A_ST = BM * (BK / 2) * 2;    // 8 KB  (comp rows of 64 B)
static constexpr int B_ST = BK * BN * 2;          // 32 KB (rows of 512 B)
static constexpr int STG  = A_ST + B_ST;          // 40 KB
static constexpr int SMEM_BYTES = STAGES * STG;   // 200 KB
static constexpr int SEGS = KK / 32;              // 128 metadata segs per row
static constexpr int RES_CAP = 32;

__device__ __align__(128) __half   g_Ac[(size_t)MM * (KK / 2)];       // 64 MB comp A
__device__ __align__(128) uint32_t g_meta[(size_t)(MM / 16) * SEGS * 16]; // 8 MB
__device__ __align__(128) __half   g_W[(size_t)KK * NN];              // 32 MB [K,N]
__device__ int            g_rescnt[MM];
__device__ unsigned short g_resk[(size_t)MM * RES_CAP];

// ---------------------------------------------------------------- helpers
__device__ __forceinline__ uint32_t smem_u32(const void* p) {
    uint32_t a;
    asm("{ .reg .u64 t; cvta.to.shared.u64 t, %1; cvt.u32.u64 %0, t; }"
        : "=r"(a) : "l"(p));
    return a;
}
__device__ __forceinline__ void cp16(uint32_t dst, const void* src) {
    asm volatile("cp.async.cg.shared.global [%0], [%1], 16;"
                 :: "r"(dst), "l"(src) : "memory");
}
__device__ __forceinline__ uint32_t swzB(uint32_t off) { return off ^ ((off >> 5) & 0x70); }
// comp-A tile: 64B rows; XOR (row>>1)&3 into 16B-chunk select -> conflict-free
__device__ __forceinline__ uint32_t swzC(uint32_t off) { return off ^ ((off >> 3) & 0x30); }

#define LDSM4(R, addr)                                                          \
    asm volatile("ldmatrix.sync.aligned.m8n8.x4.shared.b16 {%0,%1,%2,%3}, [%4];"\
                 : "=r"((R)[0]), "=r"((R)[1]), "=r"((R)[2]), "=r"((R)[3])       \
                 : "r"(addr))
#define LDSM4T(R, addr)                                                         \
    asm volatile("ldmatrix.sync.aligned.m8n8.x4.trans.shared.b16 {%0,%1,%2,%3}, [%4];" \
                 : "=r"((R)[0]), "=r"((R)[1]), "=r"((R)[2]), "=r"((R)[3])       \
                 : "r"(addr))
// 2:4 sparse HMMA, K=32: A comp 4 regs, B 4 regs, meta reg, selector 0
#define MMASP(C, A, B, E)                                                       \
    asm volatile("mma.sp::ordered_metadata.sync.aligned.m16n8k32.row.col.f32.f16.f16.f32 " \
                 "{%0,%1,%2,%3}, {%4,%5,%6,%7}, {%8,%9,%10,%11}, {%0,%1,%2,%3}, %12, 0x0;" \
                 : "+f"((C)[0]), "+f"((C)[1]), "+f"((C)[2]), "+f"((C)[3])       \
                 : "r"((A)[0]), "r"((A)[1]), "r"((A)[2]), "r"((A)[3]),          \
                   "r"((B)[0]), "r"((B)[1]), "r"((B)[2]), "r"((B)[3]),          \
                   "r"((E)))

// ---------------------------------------------------------------- pack (2:4)
// One block per row. Thread t handles k [t*16, t*16+16) = 4 groups = one
// 16-bit metadata half (seg = t>>1, p = t&1).
__global__ void __launch_bounds__(256)
pack_spike(const float4* __restrict__ src) {
    __shared__ unsigned scnt;
    __shared__ unsigned short sres[RES_CAP + 8];
    const int m = blockIdx.x;
    const int t = threadIdx.x;
    if (t == 0) scnt = 0;
    __syncthreads();

    const float4* rp = src + (size_t)m * (KK / 4) + t * 4;
    uint32_t cw[4];
    uint32_t meta16 = 0;
#pragma unroll
    for (int g = 0; g < 4; g++) {
        const float4 v = rp[g];
        const uint32_t msk = (uint32_t)(v.x != 0.f) | ((uint32_t)(v.y != 0.f) << 1)
                           | ((uint32_t)(v.z != 0.f) << 2) | ((uint32_t)(v.w != 0.f) << 3);
        const uint32_t rem = msk & (msk - 1);
        uint32_t rem2 = rem & (rem - 1);
        int i0, i1; uint32_t v0, v1;
        if (msk == 0u) { i0 = 0; i1 = 1; v0 = 0u; v1 = 0u; }
        else if (rem == 0u) {
            const int p = __ffs(msk) - 1;
            if (p < 3) { i0 = p; i1 = 3; v0 = 0x3C00u; v1 = 0u; }
            else       { i0 = 0; i1 = 3; v0 = 0u;      v1 = 0x3C00u; }
        } else {
            i0 = __ffs(msk) - 1; i1 = __ffs(rem) - 1; v0 = v1 = 0x3C00u;
            while (rem2) {                       // dropped 3rd/4th spikes
                const int pr = __ffs(rem2) - 1;
                rem2 &= rem2 - 1;
                const unsigned pos = atomicAdd(&scnt, 1u);
                if (pos < RES_CAP) sres[pos] = (unsigned short)(t * 16 + g * 4 + pr);
            }
        }
        cw[g] = v0 | (v1 << 16);
        meta16 |= (uint32_t)(i0 | (i1 << 2)) << (g * 4);
    }
    // compressed values: 8 f16 = 16 B, coalesced
    reinterpret_cast<uint4*>(g_Ac)[(size_t)m * (KK / 2 / 8) + t] = *reinterpret_cast<uint4*>(cw);
    // metadata in per-thread mma.sp format:
    // word[(mtile*SEGS+seg)*16 + q*2 + p] = { lo16: row mtile*16+q, hi16: row +8 }
    {
        const int seg = t >> 1, p = t & 1;
        const int mt = m >> 4, q = m & 7, h = (m >> 3) & 1;
        reinterpret_cast<unsigned short*>(g_meta)[
            ((size_t)(mt * SEGS + seg) * 16 + q * 2 + p) * 2 + h] = (unsigned short)meta16;
    }
    __syncthreads();
    const unsigned cnt = scnt < RES_CAP ? scnt : RES_CAP;
    if (t == 0) g_rescnt[m] = (int)cnt;
    if (t < (int)cnt) g_resk[(size_t)m * RES_CAP + t] = sres[t];
}

__global__ void cvt_w(const float4* __restrict__ src) {
    const size_t n4 = (size_t)KK * NN / 4;
    const size_t stride = (size_t)gridDim.x * blockDim.x;
    uint2* dst = reinterpret_cast<uint2*>(g_W);
    for (size_t i = (size_t)blockIdx.x * blockDim.x + threadIdx.x; i < n4; i += stride) {
        float4 v = src[i];
        __half2 a = __floats2half2_rn(v.x, v.y);
        __half2 b = __floats2half2_rn(v.z, v.w);
        uint2 p;
        p.x = *reinterpret_cast<uint32_t*>(&a);
        p.y = *reinterpret_cast<uint32_t*>(&b);
        dst[i] = p;
    }
}

// ---------------------------------------------------------------- GEMM
__global__ void __launch_bounds__(256, 1)
gemm_sp_kernel(const float* __restrict__ bias, float* __restrict__ out) {
    extern __shared__ __align__(1024) unsigned char smem[];
    const uint32_t sb = smem_u32(smem);

    const int tid = threadIdx.x;
    const int lane = tid & 31;
    const int wid = tid >> 5;
    const int wm = wid >> 2;            // 0..1 : M half (64 rows)
    const int wn = wid & 3;             // 0..3 : N quarter (64 cols)
    const int tile_n = blockIdx.x & 15; // N fastest -> W L2-resident
    const int tile_m = blockIdx.x >> 4;

    const __half* Acb = g_Ac + (size_t)(tile_m * BM) * (KK / 2);
    const __half* Bb  = g_W + tile_n * BN;

    auto load_tile = [&](int s, int t) {
        const uint32_t sA = sb + s * STG;
        const uint32_t sB = sA + A_ST;
#pragma unroll
        for (int q = 0; q < 2; q++) {                 // comp A: 128 rows x 4 x 16B
            const int idx = tid + q * 256;
            const int r = idx >> 2, c = idx & 3;
            cp16(sA + swzC((uint32_t)(r * 64 + c * 16)),
                 Acb + (size_t)r * (KK / 2) + t * 32 + c * 8);
        }
        const __half* bsrc = Bb + (size_t)(t * BK) * NN;
#pragma unroll
        for (int q = 0; q < 8; q++) {                 // B: 64 rows x 32 x 16B
            const int idx = tid + q * 256;
            const int r = idx >> 5, c = idx & 31;
            cp16(sB + swzB((uint32_t)(r * 512 + c * 16)), bsrc + (size_t)r * NN + c * 8);
        }
    };

#pragma unroll
    for (int s = 0; s < STAGES - 1; s++) {
        load_tile(s, s);
        asm volatile("cp.async.commit_group;");
    }

    float acc[4][8][4];
#pragma unroll
    for (int i = 0; i < 4; i++)
#pragma unroll
        for (int j = 0; j < 8; j++)
#pragma unroll
            for (int q = 0; q < 4; q++) acc[i][j][q] = 0.0f;

    const int mtb = tile_m * 8 + wm * 4;              // base 16-row m-tile index

#pragma unroll 1
    for (int t = 0; t < KTILES; t++) {
        asm volatile("cp.async.wait_group %0;" :: "n"(STAGES - 2));
        __syncthreads();
        if (t + STAGES - 1 < KTILES) load_tile((t + STAGES - 1) % STAGES, t + STAGES - 1);
        asm volatile("cp.async.commit_group;");

        const uint32_t sA = sb + (t % STAGES) * STG;
        const uint32_t sB = sA + A_ST;
#pragma unroll
        for (int ks = 0; ks < 2; ks++) {              // two k32 steps per BK=64
            // A comp fragments (16 comp cols per kstep)
            uint32_t a[4][4];
#pragma unroll
            for (int i = 0; i < 4; i++) {
                const int row = wm * 64 + i * 16 + (lane & 15);
                const int c = ks * 2 + (lane >> 4);
                LDSM4(a[i], sA + swzC((uint32_t)(row * 64 + c * 16)));
            }
            // B fragments: 4 regs per n8 tile (k0-15 + k16-31)
            uint32_t b[4][8];
#pragma unroll
            for (int j = 0; j < 4; j++) {
                const int colb = (wn * 64 + j * 16 + (lane >> 4) * 8) * 2;
                uint32_t lo[4], hi[4];
                LDSM4T(lo, sB + swzB((uint32_t)(((ks * 2) * 16 + (lane & 15)) * 512 + colb)));
                LDSM4T(hi, sB + swzB((uint32_t)(((ks * 2 + 1) * 16 + (lane & 15)) * 512 + colb)));
                b[j][0] = lo[0]; b[j][1] = lo[1]; b[j][2] = hi[0]; b[j][3] = hi[1];
                b[j][4] = lo[2]; b[j][5] = lo[3]; b[j][6] = hi[2]; b[j][7] = hi[3];
            }
            // metadata (L2-resident, per-thread format)
            uint32_t e[4];
            const int seg = t * 2 + ks;
#pragma unroll
            for (int i = 0; i < 4; i++)
                e[i] = __ldg(&g_meta[(size_t)((mtb + i) * SEGS + seg) * 16
                                     + (lane >> 2) * 2 + (lane & 1)]);
#pragma unroll
            for (int i = 0; i < 4; i++)
#pragma unroll
                for (int jj = 0; jj < 8; jj++)
                    MMASP(acc[i][jj], a[i], b[jj >> 1] + (jj & 1) * 4, e[i]);
        }
    }
    asm volatile("cp.async.wait_all;");

    // -------- residual fixup: add dropped spikes' W rows (exact)
#pragma unroll 1
    for (int i = 0; i < 4; i++) {
#pragma unroll 1
        for (int h = 0; h < 2; h++) {
            const int row = tile_m * 128 + wm * 64 + i * 16 + h * 8 + (lane >> 2);
            const int cnt = g_rescnt[row];
#pragma unroll 1
            for (int j = 0; j < cnt; j++) {
                const int k = g_resk[(size_t)row * RES_CAP + j];
                const __half* wp = g_W + (size_t)k * NN + tile_n * 256 + wn * 64 + (lane & 3) * 2;
#pragma unroll
                for (int jj = 0; jj < 8; jj++) {
                    const __half2 w2 = *reinterpret_cast<const __half2*>(wp + jj * 8);
                    acc[i][jj][h * 2 + 0] += __low2float(w2);
                    acc[i][jj][h * 2 + 1] += __high2float(w2);
                }
            }
        }
    }

    // -------- bias + store
    float2 bv[8];
#pragma unroll
    for (int jj = 0; jj < 8; jj++)
        bv[jj] = *reinterpret_cast<const float2*>(
            bias + tile_n * 256 + wn * 64 + jj * 8 + (lane & 3) * 2);

#pragma unroll
    for (int i = 0; i < 4; i++) {
        const int r = tile_m * 128 + wm * 64 + i * 16 + (lane >> 2);
        float* o0 = out + (size_t)r * NN + tile_n * 256 + wn * 64 + (lane & 3) * 2;
        float* o1 = o0 + (size_t)8 * NN;
#pragma unroll
        for (int jj = 0; jj < 8; jj++) {
            float2 v0 = { acc[i][jj][0] + bv[jj].x, acc[i][jj][1] + bv[jj].y };
            float2 v1 = { acc[i][jj][2] + bv[jj].x, acc[i][jj][3] + bv[jj].y };
            *reinterpret_cast<float2*>(o0 + jj * 8) = v0;
            *reinterpret_cast<float2*>(o1 + jj * 8) = v1;
        }
    }
}

// ---------------------------------------------------------------- launch
extern "C" void kernel_launch(void* const* d_in, const int* in_sizes, int n_in,
                              void* d_out, int out_size) {
    const float* sparse = (const float*)d_in[0];
    const float* weight = (const float*)d_in[1];
    const float* bias   = (const float*)d_in[2];
    float* out = (float*)d_out;

    cudaFuncSetAttribute(gemm_sp_kernel,
                         cudaFuncAttributeMaxDynamicSharedMemorySize, SMEM_BYTES);

    pack_spike<<<MM, 256>>>(reinterpret_cast<const float4*>(sparse));
    cvt_w<<<2048, 256>>>(reinterpret_cast<const float4*>(weight));
    gemm_sp_kernel<<<(MM / BM) * (NN / BN), 256, SMEM_BYTES>>>(bias, out);
}

// round 8
// speedup vs baseline: 4.4551x; 4.4551x over previous
#include <cuda_runtime.h>
#include <cuda_fp16.h>
#include <cstdint>
#include <cstddef>

// ----------------------------------------------------------------------------
// out[16384,4096] = spike[16384,4096] @ W[4096,4096] + bias   (fp32 I/O)
// Dense fp16 legacy HMMA. Round 8: BM=BN=128, 2 CTAs/SM (4 warps/SMSP),
// CORRECT warp tiling (each warp 64 rows x 32 cols, i<4), proven round-2
// mainloop structure and operand paths. No fragment double-buffer (register
// cap 128 for occupancy 2).
// ----------------------------------------------------------------------------

static constexpr int MM = 16384, KK = 4096, NN = 4096;
static constexpr int BM = 128, BN = 128, BK = 64;
static constexpr int STAGES = 3;
static constexpr int KTILES = KK / BK;           // 64
static constexpr int A_ST = BM * BK * 2;         // 16 KB (128B rows)
static constexpr int B_ST = BK * BN * 2;         // 16 KB (256B rows)
static constexpr int STG  = A_ST + B_ST;         // 32 KB
static constexpr int SMEM_BYTES = STAGES * STG;  // 96 KB -> 2 CTAs/SM

__device__ __align__(128) __half g_S[(size_t)MM * KK];   // 128 MB fp16 spikes
__device__ __align__(128) __half g_W[(size_t)KK * NN];   //  32 MB fp16 W [K,N]

// ---------------------------------------------------------------- helpers
__device__ __forceinline__ uint32_t smem_u32(const void* p) {
    uint32_t a;
    asm("{ .reg .u64 t; cvta.to.shared.u64 t, %1; cvt.u32.u64 %0, t; }"
        : "=r"(a) : "l"(p));
    return a;
}
__device__ __forceinline__ void cp16(uint32_t dst, const void* src) {
    asm volatile("cp.async.cg.shared.global [%0], [%1], 16;"
                 :: "r"(dst), "l"(src) : "memory");
}
__device__ __forceinline__ uint32_t swzA(uint32_t off) { return off ^ ((off >> 3) & 0x70); }
// 256B rows: XOR k-row%8 (bits 8-10) into 16B-chunk select (bits 4-6)
__device__ __forceinline__ uint32_t swzB(uint32_t off) { return off ^ ((off >> 4) & 0x70); }

#define LDSM4(R, addr)                                                          \
    asm volatile("ldmatrix.sync.aligned.m8n8.x4.shared.b16 {%0,%1,%2,%3}, [%4];"\
                 : "=r"((R)[0]), "=r"((R)[1]), "=r"((R)[2]), "=r"((R)[3])       \
                 : "r"(addr))
#define LDSM4T(R, addr)                                                         \
    asm volatile("ldmatrix.sync.aligned.m8n8.x4.trans.shared.b16 {%0,%1,%2,%3}, [%4];" \
                 : "=r"((R)[0]), "=r"((R)[1]), "=r"((R)[2]), "=r"((R)[3])       \
                 : "r"(addr))
#define MMA16816(C, A, B)                                                       \
    asm volatile("mma.sync.aligned.m16n8k16.row.col.f32.f16.f16.f32 "           \
                 "{%0,%1,%2,%3}, {%4,%5,%6,%7}, {%8,%9}, {%0,%1,%2,%3};"        \
                 : "+f"((C)[0]), "+f"((C)[1]), "+f"((C)[2]), "+f"((C)[3])       \
                 : "r"((A)[0]), "r"((A)[1]), "r"((A)[2]), "r"((A)[3]),          \
                   "r"((B)[0]), "r"((B)[1]))

// ---------------------------------------------------------------- converts
__global__ void cvt_f32_f16(const float4* __restrict__ src, uint2* __restrict__ dst,
                            size_t n4) {
    const size_t stride = (size_t)gridDim.x * blockDim.x;
    for (size_t i = (size_t)blockIdx.x * blockDim.x + threadIdx.x; i < n4; i += stride) {
        float4 v = src[i];
        __half2 a = __floats2half2_rn(v.x, v.y);
        __half2 b = __floats2half2_rn(v.z, v.w);
        uint2 p;
        p.x = *reinterpret_cast<uint32_t*>(&a);
        p.y = *reinterpret_cast<uint32_t*>(&b);
        dst[i] = p;
    }
}

// ---------------------------------------------------------------- GEMM
__global__ void __launch_bounds__(256, 2)
gemm_hmma_kernel(const float* __restrict__ bias, float* __restrict__ out) {
    extern __shared__ __align__(1024) unsigned char smem[];
    const uint32_t sb = smem_u32(smem);

    const int tid = threadIdx.x;
    const int lane = tid & 31;
    const int wid = tid >> 5;
    const int wm = wid >> 2;            // 0..1 : M half (64 rows)
    const int wn = wid & 3;             // 0..3 : N quarter (32 cols)
    const int tile_n = blockIdx.x & 31; // N fastest -> W stays L2-resident
    const int tile_m = blockIdx.x >> 5;

    const __half* Ab = g_S + (size_t)(tile_m * BM) * KK;
    const __half* Bb = g_W + tile_n * BN;

    auto load_tile = [&](int s, int t) {
        const uint32_t sA = sb + s * STG;
        const uint32_t sB = sA + A_ST;
#pragma unroll
        for (int q = 0; q < 4; q++) {                 // A: 128 rows x 8 x 16B
            const int idx = tid + q * 256;
            const int r = idx >> 3, c = idx & 7;
            cp16(sA + swzA((uint32_t)(r * 128 + c * 16)), Ab + (size_t)r * KK + t * BK + c * 8);
        }
        const __half* bsrc = Bb + (size_t)(t * BK) * NN;
#pragma unroll
        for (int q = 0; q < 4; q++) {                 // B: 64 k-rows x 16 x 16B
            const int idx = tid + q * 256;
            const int r = idx >> 4, c = idx & 15;
            cp16(sB + swzB((uint32_t)(r * 256 + c * 16)), bsrc + (size_t)r * NN + c * 8);
        }
    };

    // -------- prologue
#pragma unroll
    for (int s = 0; s < STAGES - 1; s++) {
        load_tile(s, s);
        asm volatile("cp.async.commit_group;");
    }

    float acc[4][4][4];
#pragma unroll
    for (int i = 0; i < 4; i++)
#pragma unroll
        for (int j = 0; j < 4; j++)
#pragma unroll
            for (int q = 0; q < 4; q++) acc[i][j][q] = 0.0f;

#pragma unroll 1
    for (int t = 0; t < KTILES; t++) {
        asm volatile("cp.async.wait_group %0;" :: "n"(STAGES - 2));
        __syncthreads();
        if (t + STAGES - 1 < KTILES) load_tile((t + STAGES - 1) % STAGES, t + STAGES - 1);
        asm volatile("cp.async.commit_group;");

        const uint32_t sA = sb + (t % STAGES) * STG;
        const uint32_t sB = sA + A_ST;
#pragma unroll
        for (int kc = 0; kc < 4; kc++) {
            uint32_t a[4][4];
#pragma unroll
            for (int i = 0; i < 4; i++) {             // 4 m16 tiles -> 64 rows
                const int row = wm * 64 + i * 16 + (lane & 15);
                LDSM4(a[i], sA + swzA((uint32_t)(row * 128 + (kc * 2 + (lane >> 4)) * 16)));
            }
            uint32_t b[2][4];
#pragma unroll
            for (int j = 0; j < 2; j++) {             // 2 n16 groups -> 32 cols
                const int krow = kc * 16 + (lane & 15);
                const int colb = (wn * 32 + j * 16 + (lane >> 4) * 8) * 2;
                LDSM4T(b[j], sB + swzB((uint32_t)(krow * 256 + colb)));
            }
#pragma unroll
            for (int i = 0; i < 4; i++)
#pragma unroll
                for (int jj = 0; jj < 4; jj++)
                    MMA16816(acc[i][jj], a[i], b[jj >> 1] + (jj & 1) * 2);
        }
    }
    asm volatile("cp.async.wait_all;");

    // -------- epilogue: bias + direct fp32 stores
    float2 bv[4];
#pragma unroll
    for (int jj = 0; jj < 4; jj++)
        bv[jj] = *reinterpret_cast<const float2*>(
            bias + tile_n * BN + wn * 32 + jj * 8 + (lane & 3) * 2);

#pragma unroll
    for (int i = 0; i < 4; i++) {
        const int r = tile_m * BM + wm * 64 + i * 16 + (lane >> 2);
        float* o0 = out + (size_t)r * NN + tile_n * BN + wn * 32 + (lane & 3) * 2;
        float* o1 = o0 + (size_t)8 * NN;
#pragma unroll
        for (int jj = 0; jj < 4; jj++) {
            float2 v0 = { acc[i][jj][0] + bv[jj].x, acc[i][jj][1] + bv[jj].y };
            float2 v1 = { acc[i][jj][2] + bv[jj].x, acc[i][jj][3] + bv[jj].y };
            *reinterpret_cast<float2*>(o0 + jj * 8) = v0;
            *reinterpret_cast<float2*>(o1 + jj * 8) = v1;
        }
    }
}

// ---------------------------------------------------------------- launch
extern "C" void kernel_launch(void* const* d_in, const int* in_sizes, int n_in,
                              void* d_out, int out_size) {
    const float* sparse = (const float*)d_in[0];
    const float* weight = (const float*)d_in[1];
    const float* bias   = (const float*)d_in[2];
    float* out = (float*)d_out;

    cudaFuncSetAttribute(gemm_hmma_kernel,
                         cudaFuncAttributeMaxDynamicSharedMemorySize, SMEM_BYTES);

    __half* dS; cudaGetSymbolAddress((void**)&dS, g_S);
    __half* dW; cudaGetSymbolAddress((void**)&dW, g_W);

    cvt_f32_f16<<<4096, 256>>>(reinterpret_cast<const float4*>(sparse),
                               reinterpret_cast<uint2*>(dS), (size_t)MM * KK / 4);
    cvt_f32_f16<<<2048, 256>>>(reinterpret_cast<const float4*>(weight),
                               reinterpret_cast<uint2*>(dW), (size_t)KK * NN / 4);
    gemm_hmma_kernel<<<(MM / BM) * (NN / BN), 256, SMEM_BYTES>>>(bias, out);
}

// round 9
// speedup vs baseline: 4.4861x; 1.0069x over previous
#include <cuda_runtime.h>
#include <cuda_fp16.h>
#include <cstdint>
#include <cstddef>

// ----------------------------------------------------------------------------
// out[16384,4096] = spike[16384,4096] @ W[4096,4096] + bias   (fp32 I/O)
// Dense fp16 legacy HMMA at its measured issue floor. Round 9 consolidation:
//  - single merged cvt kernel (S and W in one DRAM-bound launch)
//  - refill cp.asyncs spread across kc iterations (smooth LSU pressure)
//  - t-loop unrolled x3 so stage offsets are immediates
// Core GEMM identical to round 8 (BM=BN=128, BK=64, 3 stages, 2 CTAs/SM).
// ----------------------------------------------------------------------------

static constexpr int MM = 16384, KK = 4096, NN = 4096;
static constexpr int BM = 128, BN = 128, BK = 64;
static constexpr int STAGES = 3;
static constexpr int KTILES = KK / BK;           // 64 (divisible by 3? no: handled by unroll pattern)
static constexpr int A_ST = BM * BK * 2;         // 16 KB (128B rows)
static constexpr int B_ST = BK * BN * 2;         // 16 KB (256B rows)
static constexpr int STG  = A_ST + B_ST;         // 32 KB
static constexpr int SMEM_BYTES = STAGES * STG;  // 96 KB -> 2 CTAs/SM

__device__ __align__(128) __half g_S[(size_t)MM * KK];   // 128 MB fp16 spikes
__device__ __align__(128) __half g_W[(size_t)KK * NN];   //  32 MB fp16 W [K,N]

// ---------------------------------------------------------------- helpers
__device__ __forceinline__ uint32_t smem_u32(const void* p) {
    uint32_t a;
    asm("{ .reg .u64 t; cvta.to.shared.u64 t, %1; cvt.u32.u64 %0, t; }"
        : "=r"(a) : "l"(p));
    return a;
}
__device__ __forceinline__ void cp16(uint32_t dst, const void* src) {
    asm volatile("cp.async.cg.shared.global [%0], [%1], 16;"
                 :: "r"(dst), "l"(src) : "memory");
}
__device__ __forceinline__ uint32_t swzA(uint32_t off) { return off ^ ((off >> 3) & 0x70); }
__device__ __forceinline__ uint32_t swzB(uint32_t off) { return off ^ ((off >> 4) & 0x70); }

#define LDSM4(R, addr)                                                          \
    asm volatile("ldmatrix.sync.aligned.m8n8.x4.shared.b16 {%0,%1,%2,%3}, [%4];"\
                 : "=r"((R)[0]), "=r"((R)[1]), "=r"((R)[2]), "=r"((R)[3])       \
                 : "r"(addr))
#define LDSM4T(R, addr)                                                         \
    asm volatile("ldmatrix.sync.aligned.m8n8.x4.trans.shared.b16 {%0,%1,%2,%3}, [%4];" \
                 : "=r"((R)[0]), "=r"((R)[1]), "=r"((R)[2]), "=r"((R)[3])       \
                 : "r"(addr))
#define MMA16816(C, A, B)                                                       \
    asm volatile("mma.sync.aligned.m16n8k16.row.col.f32.f16.f16.f32 "           \
                 "{%0,%1,%2,%3}, {%4,%5,%6,%7}, {%8,%9}, {%0,%1,%2,%3};"        \
                 : "+f"((C)[0]), "+f"((C)[1]), "+f"((C)[2]), "+f"((C)[3])       \
                 : "r"((A)[0]), "r"((A)[1]), "r"((A)[2]), "r"((A)[3]),          \
                   "r"((B)[0]), "r"((B)[1]))

// ---------------------------------------------------------------- merged cvt
// one launch converts both S (128M elems) and W (16M elems) fp32 -> fp16
__global__ void cvt_all(const float4* __restrict__ s_src, const float4* __restrict__ w_src) {
    const size_t stride = (size_t)gridDim.x * blockDim.x;
    const size_t tid0 = (size_t)blockIdx.x * blockDim.x + threadIdx.x;
    uint2* sdst = reinterpret_cast<uint2*>(g_S);
    uint2* wdst = reinterpret_cast<uint2*>(g_W);
    const size_t nS = (size_t)MM * KK / 4;
    const size_t nW = (size_t)KK * NN / 4;
    for (size_t i = tid0; i < nS; i += stride) {
        float4 v = s_src[i];
        __half2 a = __floats2half2_rn(v.x, v.y);
        __half2 b = __floats2half2_rn(v.z, v.w);
        uint2 p;
        p.x = *reinterpret_cast<uint32_t*>(&a);
        p.y = *reinterpret_cast<uint32_t*>(&b);
        sdst[i] = p;
    }
    for (size_t i = tid0; i < nW; i += stride) {
        float4 v = w_src[i];
        __half2 a = __floats2half2_rn(v.x, v.y);
        __half2 b = __floats2half2_rn(v.z, v.w);
        uint2 p;
        p.x = *reinterpret_cast<uint32_t*>(&a);
        p.y = *reinterpret_cast<uint32_t*>(&b);
        wdst[i] = p;
    }
}

// ---------------------------------------------------------------- GEMM
__global__ void __launch_bounds__(256, 2)
gemm_hmma_kernel(const float* __restrict__ bias, float* __restrict__ out) {
    extern __shared__ __align__(1024) unsigned char smem[];
    const uint32_t sb = smem_u32(smem);

    const int tid = threadIdx.x;
    const int lane = tid & 31;
    const int wid = tid >> 5;
    const int wm = wid >> 2;            // 0..1 : M half (64 rows)
    const int wn = wid & 3;             // 0..3 : N quarter (32 cols)
    const int tile_n = blockIdx.x & 31; // N fastest -> W stays L2-resident
    const int tile_m = blockIdx.x >> 5;

    const __half* Ab = g_S + (size_t)(tile_m * BM) * KK;
    const __half* Bb = g_W + tile_n * BN;

    // precomputed per-thread load slots
    const int arow = tid >> 3, acol = tid & 7;            // A: 2 rows apart x4
    const int brow = tid >> 4, bcol = tid & 15;           // B: 4 rows apart x4
    const uint32_t aoff0 = swzA((uint32_t)(arow * 128 + acol * 16));
    const uint32_t boff0 = swzB((uint32_t)(brow * 256 + bcol * 16));

    // issue 1/4 of the refill for stage s, tile t (q = 0..3)
    auto load_q = [&](int s, int t, int q) {
        const uint32_t sA = sb + s * STG;
        const int r = arow + q * 32;
        cp16(sA + swzA((uint32_t)(r * 128 + acol * 16)),
             Ab + (size_t)r * KK + t * BK + acol * 8);
        const uint32_t sB = sA + A_ST;
        const int rb = brow + q * 16;
        cp16(sB + swzB((uint32_t)(rb * 256 + bcol * 16)),
             Bb + (size_t)(t * BK + rb) * NN + bcol * 8);
    };
    auto load_tile = [&](int s, int t) {
#pragma unroll
        for (int q = 0; q < 4; q++) load_q(s, t, q);
    };

    // -------- prologue
#pragma unroll
    for (int s = 0; s < STAGES - 1; s++) {
        load_tile(s, s);
        asm volatile("cp.async.commit_group;");
    }

    float acc[4][4][4];
#pragma unroll
    for (int i = 0; i < 4; i++)
#pragma unroll
        for (int j = 0; j < 4; j++)
#pragma unroll
            for (int q = 0; q < 4; q++) acc[i][j][q] = 0.0f;

#pragma unroll 1
    for (int tb = 0; tb < KTILES; tb += STAGES) {
#pragma unroll
        for (int ts = 0; ts < STAGES; ts++) {            // stage index == ts (immediates)
            const int t = tb + ts;
            if (t >= KTILES) break;
            asm volatile("cp.async.wait_group %0;" :: "n"(STAGES - 2));
            __syncthreads();

            const uint32_t sA = sb + ts * STG;
            const uint32_t sB = sA + A_ST;
            const int tn = t + STAGES - 1;               // refill target tile
            const int sn = tn % STAGES;                  // == (ts+2)%3, constant per ts
            const bool do_refill = (tn < KTILES);

#pragma unroll
            for (int kc = 0; kc < 4; kc++) {
                // spread refill: one quarter per kc
                if (do_refill) load_q(sn, tn, kc);

                uint32_t a[4][4];
#pragma unroll
                for (int i = 0; i < 4; i++) {
                    const int row = wm * 64 + i * 16 + (lane & 15);
                    LDSM4(a[i], sA + swzA((uint32_t)(row * 128 + (kc * 2 + (lane >> 4)) * 16)));
                }
                uint32_t b[2][4];
#pragma unroll
                for (int j = 0; j < 2; j++) {
                    const int krow = kc * 16 + (lane & 15);
                    const int colb = (wn * 32 + j * 16 + (lane >> 4) * 8) * 2;
                    LDSM4T(b[j], sB + swzB((uint32_t)(krow * 256 + colb)));
                }
#pragma unroll
                for (int i = 0; i < 4; i++)
#pragma unroll
                    for (int jj = 0; jj < 4; jj++)
                        MMA16816(acc[i][jj], a[i], b[jj >> 1] + (jj & 1) * 2);
            }
            asm volatile("cp.async.commit_group;");
        }
    }
    asm volatile("cp.async.wait_all;");

    // -------- epilogue: bias + direct fp32 stores
    float2 bv[4];
#pragma unroll
    for (int jj = 0; jj < 4; jj++)
        bv[jj] = *reinterpret_cast<const float2*>(
            bias + tile_n * BN + wn * 32 + jj * 8 + (lane & 3) * 2);

#pragma unroll
    for (int i = 0; i < 4; i++) {
        const int r = tile_m * BM + wm * 64 + i * 16 + (lane >> 2);
        float* o0 = out + (size_t)r * NN + tile_n * BN + wn * 32 + (lane & 3) * 2;
        float* o1 = o0 + (size_t)8 * NN;
#pragma unroll
        for (int jj = 0; jj < 4; jj++) {
            float2 v0 = { acc[i][jj][0] + bv[jj].x, acc[i][jj][1] + bv[jj].y };
            float2 v1 = { acc[i][jj][2] + bv[jj].x, acc[i][jj][3] + bv[jj].y };
            *reinterpret_cast<float2*>(o0 + jj * 8) = v0;
            *reinterpret_cast<float2*>(o1 + jj * 8) = v1;
        }
    }
}

// ---------------------------------------------------------------- launch
extern "C" void kernel_launch(void* const* d_in, const int* in_sizes, int n_in,
                              void* d_out, int out_size) {
    const float* sparse = (const float*)d_in[0];
    const float* weight = (const float*)d_in[1];
    const float* bias   = (const float*)d_in[2];
    float* out = (float*)d_out;

    cudaFuncSetAttribute(gemm_hmma_kernel,
                         cudaFuncAttributeMaxDynamicSharedMemorySize, SMEM_BYTES);

    cvt_all<<<4096, 256>>>(reinterpret_cast<const float4*>(sparse),
                           reinterpret_cast<const float4*>(weight));
    gemm_hmma_kernel<<<(MM / BM) * (NN / BN), 256, SMEM_BYTES>>>(bias, out);
}

// round 10
// speedup vs baseline: 4.4959x; 1.0022x over previous
#include <cuda_runtime.h>
#include <cuda_fp16.h>
#include <cstdint>
#include <cstddef>

// ----------------------------------------------------------------------------
// out[16384,4096] = spike[16384,4096] @ W[4096,4096] + bias   (fp32 I/O)
// Dense fp16 legacy HMMA at its issue floor (~95% of 1.81M cyc @ ~1.5GHz).
// Round 10 consolidation: streaming cache hints (.cs) on the output and the
// S fp16 stream to protect W/A L2 residency; core GEMM identical to round 9.
// ----------------------------------------------------------------------------

static constexpr int MM = 16384, KK = 4096, NN = 4096;
static constexpr int BM = 128, BN = 128, BK = 64;
static constexpr int STAGES = 3;
static constexpr int KTILES = KK / BK;           // 64
static constexpr int A_ST = BM * BK * 2;         // 16 KB (128B rows)
static constexpr int B_ST = BK * BN * 2;         // 16 KB (256B rows)
static constexpr int STG  = A_ST + B_ST;         // 32 KB
static constexpr int SMEM_BYTES = STAGES * STG;  // 96 KB -> 2 CTAs/SM

__device__ __align__(128) __half g_S[(size_t)MM * KK];   // 128 MB fp16 spikes
__device__ __align__(128) __half g_W[(size_t)KK * NN];   //  32 MB fp16 W [K,N]

// ---------------------------------------------------------------- helpers
__device__ __forceinline__ uint32_t smem_u32(const void* p) {
    uint32_t a;
    asm("{ .reg .u64 t; cvta.to.shared.u64 t, %1; cvt.u32.u64 %0, t; }"
        : "=r"(a) : "l"(p));
    return a;
}
__device__ __forceinline__ void cp16(uint32_t dst, const void* src) {
    asm volatile("cp.async.cg.shared.global [%0], [%1], 16;"
                 :: "r"(dst), "l"(src) : "memory");
}
__device__ __forceinline__ void st_cs_v2(float* p, float x, float y) {
    asm volatile("st.global.cs.v2.f32 [%0], {%1, %2};" :: "l"(p), "f"(x), "f"(y) : "memory");
}
__device__ __forceinline__ void st_cs_v4(void* p, uint2 a, uint2 b) {
    asm volatile("st.global.cs.v4.b32 [%0], {%1, %2, %3, %4};"
                 :: "l"(p), "r"(a.x), "r"(a.y), "r"(b.x), "r"(b.y) : "memory");
}
__device__ __forceinline__ uint32_t swzA(uint32_t off) { return off ^ ((off >> 3) & 0x70); }
__device__ __forceinline__ uint32_t swzB(uint32_t off) { return off ^ ((off >> 4) & 0x70); }

#define LDSM4(R, addr)                                                          \
    asm volatile("ldmatrix.sync.aligned.m8n8.x4.shared.b16 {%0,%1,%2,%3}, [%4];"\
                 : "=r"((R)[0]), "=r"((R)[1]), "=r"((R)[2]), "=r"((R)[3])       \
                 : "r"(addr))
#define LDSM4T(R, addr)                                                         \
    asm volatile("ldmatrix.sync.aligned.m8n8.x4.trans.shared.b16 {%0,%1,%2,%3}, [%4];" \
                 : "=r"((R)[0]), "=r"((R)[1]), "=r"((R)[2]), "=r"((R)[3])       \
                 : "r"(addr))
#define MMA16816(C, A, B)                                                       \
    asm volatile("mma.sync.aligned.m16n8k16.row.col.f32.f16.f16.f32 "           \
                 "{%0,%1,%2,%3}, {%4,%5,%6,%7}, {%8,%9}, {%0,%1,%2,%3};"        \
                 : "+f"((C)[0]), "+f"((C)[1]), "+f"((C)[2]), "+f"((C)[3])       \
                 : "r"((A)[0]), "r"((A)[1]), "r"((A)[2]), "r"((A)[3]),          \
                   "r"((B)[0]), "r"((B)[1]))

// ---------------------------------------------------------------- merged cvt
// S stream written with .cs (evict-first: 128 MB, keep W resident in L2).
__global__ void cvt_all(const float4* __restrict__ s_src, const float4* __restrict__ w_src) {
    const size_t stride = (size_t)gridDim.x * blockDim.x;
    const size_t tid0 = (size_t)blockIdx.x * blockDim.x + threadIdx.x;
    uint2* sdst = reinterpret_cast<uint2*>(g_S);
    uint2* wdst = reinterpret_cast<uint2*>(g_W);
    const size_t nS = (size_t)MM * KK / 4;
    const size_t nW = (size_t)KK * NN / 4;
    for (size_t i = tid0; i < nS; i += stride) {
        float4 v = __ldg(s_src + i);
        __half2 a = __floats2half2_rn(v.x, v.y);
        __half2 b = __floats2half2_rn(v.z, v.w);
        uint2 p;
        p.x = *reinterpret_cast<uint32_t*>(&a);
        p.y = *reinterpret_cast<uint32_t*>(&b);
        asm volatile("st.global.cs.v2.b32 [%0], {%1, %2};"
                     :: "l"(sdst + i), "r"(p.x), "r"(p.y) : "memory");
    }
    for (size_t i = tid0; i < nW; i += stride) {
        float4 v = __ldg(w_src + i);
        __half2 a = __floats2half2_rn(v.x, v.y);
        __half2 b = __floats2half2_rn(v.z, v.w);
        uint2 p;
        p.x = *reinterpret_cast<uint32_t*>(&a);
        p.y = *reinterpret_cast<uint32_t*>(&b);
        wdst[i] = p;
    }
}

// ---------------------------------------------------------------- GEMM
__global__ void __launch_bounds__(256, 2)
gemm_hmma_kernel(const float* __restrict__ bias, float* __restrict__ out) {
    extern __shared__ __align__(1024) unsigned char smem[];
    const uint32_t sb = smem_u32(smem);

    const int tid = threadIdx.x;
    const int lane = tid & 31;
    const int wid = tid >> 5;
    const int wm = wid >> 2;            // 0..1 : M half (64 rows)
    const int wn = wid & 3;             // 0..3 : N quarter (32 cols)
    const int tile_n = blockIdx.x & 31; // N fastest -> W stays L2-resident
    const int tile_m = blockIdx.x >> 5;

    const __half* Ab = g_S + (size_t)(tile_m * BM) * KK;
    const __half* Bb = g_W + tile_n * BN;

    const int arow = tid >> 3, acol = tid & 7;
    const int brow = tid >> 4, bcol = tid & 15;

    auto load_q = [&](int s, int t, int q) {
        const uint32_t sA = sb + s * STG;
        const int r = arow + q * 32;
        cp16(sA + swzA((uint32_t)(r * 128 + acol * 16)),
             Ab + (size_t)r * KK + t * BK + acol * 8);
        const uint32_t sB = sA + A_ST;
        const int rb = brow + q * 16;
        cp16(sB + swzB((uint32_t)(rb * 256 + bcol * 16)),
             Bb + (size_t)(t * BK + rb) * NN + bcol * 8);
    };
    auto load_tile = [&](int s, int t) {
#pragma unroll
        for (int q = 0; q < 4; q++) load_q(s, t, q);
    };

    // -------- prologue
#pragma unroll
    for (int s = 0; s < STAGES - 1; s++) {
        load_tile(s, s);
        asm volatile("cp.async.commit_group;");
    }

    float acc[4][4][4];
#pragma unroll
    for (int i = 0; i < 4; i++)
#pragma unroll
        for (int j = 0; j < 4; j++)
#pragma unroll
            for (int q = 0; q < 4; q++) acc[i][j][q] = 0.0f;

#pragma unroll 1
    for (int tb = 0; tb < KTILES; tb += STAGES) {
#pragma unroll
        for (int ts = 0; ts < STAGES; ts++) {            // stage index == ts (immediates)
            const int t = tb + ts;
            if (t >= KTILES) break;
            asm volatile("cp.async.wait_group %0;" :: "n"(STAGES - 2));
            __syncthreads();

            const uint32_t sA = sb + ts * STG;
            const uint32_t sB = sA + A_ST;
            const int tn = t + STAGES - 1;
            const int sn = tn % STAGES;
            const bool do_refill = (tn < KTILES);

#pragma unroll
            for (int kc = 0; kc < 4; kc++) {
                if (do_refill) load_q(sn, tn, kc);       // spread refill

                uint32_t a[4][4];
#pragma unroll
                for (int i = 0; i < 4; i++) {
                    const int row = wm * 64 + i * 16 + (lane & 15);
                    LDSM4(a[i], sA + swzA((uint32_t)(row * 128 + (kc * 2 + (lane >> 4)) * 16)));
                }
                uint32_t b[2][4];
#pragma unroll
                for (int j = 0; j < 2; j++) {
                    const int krow = kc * 16 + (lane & 15);
                    const int colb = (wn * 32 + j * 16 + (lane >> 4) * 8) * 2;
                    LDSM4T(b[j], sB + swzB((uint32_t)(krow * 256 + colb)));
                }
#pragma unroll
                for (int i = 0; i < 4; i++)
#pragma unroll
                    for (int jj = 0; jj < 4; jj++)
                        MMA16816(acc[i][jj], a[i], b[jj >> 1] + (jj & 1) * 2);
            }
            asm volatile("cp.async.commit_group;");
        }
    }
    asm volatile("cp.async.wait_all;");

    // -------- epilogue: bias + streaming fp32 stores (evict-first)
    float2 bv[4];
#pragma unroll
    for (int jj = 0; jj < 4; jj++)
        bv[jj] = *reinterpret_cast<const float2*>(
            bias + tile_n * BN + wn * 32 + jj * 8 + (lane & 3) * 2);

#pragma unroll
    for (int i = 0; i < 4; i++) {
        const int r = tile_m * BM + wm * 64 + i * 16 + (lane >> 2);
        float* o0 = out + (size_t)r * NN + tile_n * BN + wn * 32 + (lane & 3) * 2;
        float* o1 = o0 + (size_t)8 * NN;
#pragma unroll
        for (int jj = 0; jj < 4; jj++) {
            st_cs_v2(o0 + jj * 8, acc[i][jj][0] + bv[jj].x, acc[i][jj][1] + bv[jj].y);
            st_cs_v2(o1 + jj * 8, acc[i][jj][2] + bv[jj].x, acc[i][jj][3] + bv[jj].y);
        }
    }
}

// ---------------------------------------------------------------- launch
extern "C" void kernel_launch(void* const* d_in, const int* in_sizes, int n_in,
                              void* d_out, int out_size) {
    const float* sparse = (const float*)d_in[0];
    const float* weight = (const float*)d_in[1];
    const float* bias   = (const float*)d_in[2];
    float* out = (float*)d_out;

    cudaFuncSetAttribute(gemm_hmma_kernel,
                         cudaFuncAttributeMaxDynamicSharedMemorySize, SMEM_BYTES);

    cvt_all<<<4096, 256>>>(reinterpret_cast<const float4*>(sparse),
                           reinterpret_cast<const float4*>(weight));
    gemm_hmma_kernel<<<(MM / BM) * (NN / BN), 256, SMEM_BYTES>>>(bias, out);
}